// round 1
// baseline (speedup 1.0000x reference)
#include <cuda_runtime.h>
#include <cstdint>
#include <cstddef>

#define T_STEPS 2048
#define BATCH   64
#define IDIM    512
#define HDIM    512
#define GDIM    2048                 // 4*H, gate order [f|i|o|c]
#define BH      (BATCH * HDIM)       // 32768
#define NCTA_REC 128

// 1 GiB scratch for precomputed input-side gates Xg[t, b, 4H] (fp32, bias folded in)
__device__ float g_Xg[(size_t)T_STEPS * BATCH * GDIM];
__device__ unsigned int g_sync;

__device__ __forceinline__ unsigned f2tf32(float x) {
    unsigned r;
    asm("cvt.rna.tf32.f32 %0, %1;" : "=r"(r) : "f"(x));
    return r;
}

__device__ __forceinline__ void mma_tf32(float &d0, float &d1, float &d2, float &d3,
                                         unsigned a0, unsigned a1, unsigned a2, unsigned a3,
                                         unsigned b0, unsigned b1) {
    asm volatile(
        "mma.sync.aligned.m16n8k8.row.col.f32.tf32.tf32.f32 "
        "{%0,%1,%2,%3}, {%4,%5,%6,%7}, {%8,%9}, {%0,%1,%2,%3};\n"
        : "+f"(d0), "+f"(d1), "+f"(d2), "+f"(d3)
        : "r"(a0), "r"(a1), "r"(a2), "r"(a3), "r"(b0), "r"(b1));
}

__global__ void reset_kernel() { g_sync = 0u; }

// ===========================================================================
// Phase 1: Xg = X @ Wx + b   ([131072 x 512] @ [512 x 2048], tf32 mma)
// CTA tile 128x128, K-chunk 32. Each CTA's 128-wide N slab lies in exactly one gate.
// ===========================================================================
__global__ void __launch_bounds__(256, 2) xgemm_kernel(
    const float* __restrict__ X,
    const float* __restrict__ Wxf, const float* __restrict__ Wxi,
    const float* __restrict__ Wxo, const float* __restrict__ Wxc,
    const float* __restrict__ bf, const float* __restrict__ bi,
    const float* __restrict__ bo, const float* __restrict__ bc)
{
    __shared__ unsigned As[128 * 36];   // [m][k] pad 36 -> (4m+k)%32 distinct
    __shared__ unsigned Bs[128 * 36];   // [n][k] pad 36 -> (4n+k)%32 distinct

    const int tid  = threadIdx.x;
    const int warp = tid >> 5;
    const int lane = tid & 31;
    const int m0 = blockIdx.y * 128;
    const int n0 = blockIdx.x * 128;
    const int wm = (warp >> 2) * 64;    // warp grid 2(M) x 4(N), warp tile 64x32
    const int wn = (warp & 3) * 32;

    const int g    = n0 >> 9;           // gate for this CTA (uniform)
    const int col0 = n0 & 511;
    const float* Wx = (g == 0) ? Wxf : (g == 1) ? Wxi : (g == 2) ? Wxo : Wxc;
    const float* bb = (g == 0) ? bf  : (g == 1) ? bi  : (g == 2) ? bo  : bc;

    float acc[4][4][4];
    #pragma unroll
    for (int mt = 0; mt < 4; mt++)
        #pragma unroll
        for (int nt = 0; nt < 4; nt++)
            #pragma unroll
            for (int e = 0; e < 4; e++) acc[mt][nt][e] = 0.f;

    for (int k0 = 0; k0 < IDIM; k0 += 32) {
        // A tile: 128 rows x 32 cols
        #pragma unroll
        for (int i = 0; i < 4; i++) {
            int idx = tid + i * 256;                 // 0..1023 float4 slots
            int r = idx >> 3;
            int c = (idx & 7) * 4;
            float4 v = *reinterpret_cast<const float4*>(X + (size_t)(m0 + r) * IDIM + k0 + c);
            As[r * 36 + c + 0] = f2tf32(v.x);
            As[r * 36 + c + 1] = f2tf32(v.y);
            As[r * 36 + c + 2] = f2tf32(v.z);
            As[r * 36 + c + 3] = f2tf32(v.w);
        }
        // B tile: 32 k-rows x 128 n-cols, transposed into [n][k]
        #pragma unroll
        for (int i = 0; i < 4; i++) {
            int idx = tid + i * 256;
            int kr = idx >> 5;
            int nf = (idx & 31) * 4;
            float4 v = *reinterpret_cast<const float4*>(Wx + (size_t)(k0 + kr) * HDIM + col0 + nf);
            Bs[(nf + 0) * 36 + kr] = f2tf32(v.x);
            Bs[(nf + 1) * 36 + kr] = f2tf32(v.y);
            Bs[(nf + 2) * 36 + kr] = f2tf32(v.z);
            Bs[(nf + 3) * 36 + kr] = f2tf32(v.w);
        }
        __syncthreads();

        #pragma unroll
        for (int kk = 0; kk < 32; kk += 8) {
            unsigned a[4][4], b[4][2];
            const int kc = kk + (lane & 3);
            #pragma unroll
            for (int mt = 0; mt < 4; mt++) {
                int r = wm + mt * 16 + (lane >> 2);
                a[mt][0] = As[r * 36 + kc];
                a[mt][1] = As[(r + 8) * 36 + kc];
                a[mt][2] = As[r * 36 + kc + 4];
                a[mt][3] = As[(r + 8) * 36 + kc + 4];
            }
            #pragma unroll
            for (int nt = 0; nt < 4; nt++) {
                int n = wn + nt * 8 + (lane >> 2);
                b[nt][0] = Bs[n * 36 + kc];
                b[nt][1] = Bs[n * 36 + kc + 4];
            }
            #pragma unroll
            for (int mt = 0; mt < 4; mt++)
                #pragma unroll
                for (int nt = 0; nt < 4; nt++)
                    mma_tf32(acc[mt][nt][0], acc[mt][nt][1], acc[mt][nt][2], acc[mt][nt][3],
                             a[mt][0], a[mt][1], a[mt][2], a[mt][3],
                             b[nt][0], b[nt][1]);
        }
        __syncthreads();
    }

    // epilogue: + bias, fp32 store
    #pragma unroll
    for (int mt = 0; mt < 4; mt++) {
        #pragma unroll
        for (int nt = 0; nt < 4; nt++) {
            int nloc = wn + nt * 8 + (lane & 3) * 2;
            int r = m0 + wm + mt * 16 + (lane >> 2);
            float bv0 = bb[col0 + nloc];
            float bv1 = bb[col0 + nloc + 1];
            float2 v0 = make_float2(acc[mt][nt][0] + bv0, acc[mt][nt][1] + bv1);
            float2 v1 = make_float2(acc[mt][nt][2] + bv0, acc[mt][nt][3] + bv1);
            *reinterpret_cast<float2*>(&g_Xg[(size_t)r * GDIM + n0 + nloc]) = v0;
            *reinterpret_cast<float2*>(&g_Xg[(size_t)(r + 8) * GDIM + n0 + nloc]) = v1;
        }
    }
}

// ===========================================================================
// Phase 2: persistent recurrence kernel. 128 CTAs = 4 batch-tiles x 32 hidden-tiles.
// Each CTA: gates g[16 batch, 64 gate-cols] = h[16,512] @ Wh_slice[512,64] + Xg.
// Wh slice is pre-swizzled once into exact per-lane B-fragment layout in smem;
// h is re-staged into A-fragment layout each step (inner loop: LDS.128+LDS.64+HMMA).
// h feedback lives in the output buffer itself (out[t] == h_t).
// ===========================================================================
#define REC_SMEM (131072 + 32768 + 16 * 66 * 4)   // Wfrag + hfrag + gate staging

__global__ void __launch_bounds__(256, 1) lstm_rec_kernel(
    float* __restrict__ out,
    const float* __restrict__ Whf, const float* __restrict__ Whi,
    const float* __restrict__ Who, const float* __restrict__ Whc)
{
    extern __shared__ unsigned char smem_raw[];
    uint2* Wfrag = reinterpret_cast<uint2*>(smem_raw);                   // [8 warps][64 ki][32 lanes]
    uint4* hfrag = reinterpret_cast<uint4*>(smem_raw + 131072);          // [64 ki][32 lanes]
    float* gs    = reinterpret_cast<float*>(smem_raw + 131072 + 32768);  // [16][66]

    const int tid  = threadIdx.x;
    const int warp = tid >> 5;
    const int lane = tid & 31;
    const int bt = blockIdx.x >> 5;   // batch tile 0..3  (16 rows)
    const int jt = blockIdx.x & 31;   // hidden tile 0..31 (16 cols)

    // ---- one-time W_h fragment pre-swizzle (per warp: its 8 gate-cols) ----
    {
        const int gg = warp >> 1;     // gate of this warp's 8-col slice (uniform)
        const float* Wh = (gg == 0) ? Whf : (gg == 1) ? Whi : (gg == 2) ? Who : Whc;
        const int n   = warp * 8 + (lane >> 2);   // CTA gate col 0..63
        const int col = jt * 16 + (n & 15);
        const int kb  = lane & 3;
        #pragma unroll 4
        for (int ki = 0; ki < 64; ki++) {
            int k = ki * 8 + kb;
            unsigned w0 = f2tf32(Wh[(size_t)k * HDIM + col]);
            unsigned w1 = f2tf32(Wh[(size_t)(k + 4) * HDIM + col]);
            Wfrag[(warp * 64 + ki) * 32 + lane] = make_uint2(w0, w1);
        }
    }

    // elementwise mapping: one thread owns cell state c[bt*16+eb][jt*16+ej]
    const int eb = tid >> 4;
    const int ej = tid & 15;
    float c_val = 0.f;

    // D-fragment coordinates for this thread
    const int r     = lane >> 2;                      // 0..7
    const int cpair = warp * 8 + ((lane & 3) << 1);   // even gate-col 0..62
    const size_t xg_col = (size_t)(cpair >> 4) * HDIM + (size_t)jt * 16 + (cpair & 15);

    __syncthreads();

    for (int t = 0; t < T_STEPS; t++) {
        // ---- stage h_{t-1} into A-fragment layout (tf32) ----
        if (t == 0) {
            #pragma unroll
            for (int i = 0; i < 8; i++)
                hfrag[tid + i * 256] = make_uint4(0u, 0u, 0u, 0u);
        } else {
            const float* hprev = out + (size_t)(t - 1) * BH;
            #pragma unroll
            for (int i = 0; i < 8; i++) {
                int f4 = tid + i * 256;        // 0..2047
                int b  = f4 >> 7;              // local batch row 0..15
                int k4 = (f4 & 127) * 4;
                float4 v = *reinterpret_cast<const float4*>(
                    hprev + (size_t)(bt * 16 + b) * HDIM + k4);
                unsigned vals[4] = {f2tf32(v.x), f2tf32(v.y), f2tf32(v.z), f2tf32(v.w)};
                #pragma unroll
                for (int e = 0; e < 4; e++) {
                    int k  = k4 + e;
                    int ki = k >> 3;
                    int l  = ((b & 7) << 2) | (k & 3);
                    int el = (b >> 3) | ((k & 4) >> 1);  // a0/a1/a2/a3 slot
                    reinterpret_cast<unsigned*>(&hfrag[ki * 32 + l])[el] = vals[e];
                }
            }
        }

        // ---- init accumulators with precomputed Xg (bias already folded) ----
        float d0, d1, d2, d3;
        {
            size_t rowbase = ((size_t)t * BATCH + (size_t)bt * 16) * (size_t)GDIM;
            float2 x0 = *reinterpret_cast<const float2*>(&g_Xg[rowbase + (size_t)r * GDIM + xg_col]);
            float2 x1 = *reinterpret_cast<const float2*>(&g_Xg[rowbase + (size_t)(r + 8) * GDIM + xg_col]);
            d0 = x0.x; d1 = x0.y; d2 = x1.x; d3 = x1.y;
        }

        __syncthreads();   // hfrag ready

        // ---- K=512 mma loop: 64 x (LDS.128 + LDS.64 + HMMA.tf32) ----
        {
            const uint4* hp = hfrag + lane;
            const uint2* wp = Wfrag + warp * 2048 + lane;
            #pragma unroll
            for (int ki = 0; ki < 64; ki++) {
                uint4 a = hp[ki * 32];
                uint2 b = wp[ki * 32];
                mma_tf32(d0, d1, d2, d3, a.x, a.y, a.z, a.w, b.x, b.y);
            }
        }

        // ---- gate staging for cross-warp combine ----
        *reinterpret_cast<float2*>(&gs[r * 66 + cpair])       = make_float2(d0, d1);
        *reinterpret_cast<float2*>(&gs[(r + 8) * 66 + cpair]) = make_float2(d2, d3);
        __syncthreads();

        // ---- LSTM cell (one (b,j) per thread), write h_t to out ----
        {
            float gf = gs[eb * 66 +  0 + ej];
            float gi = gs[eb * 66 + 16 + ej];
            float go = gs[eb * 66 + 32 + ej];
            float gc = gs[eb * 66 + 48 + ej];
            float fg = 1.f / (1.f + __expf(-gf));
            float ig = 1.f / (1.f + __expf(-gi));
            float og = 1.f / (1.f + __expf(-go));
            float ch = 2.f / (1.f + __expf(-2.f * gc)) - 1.f;   // tanh
            c_val = fg * c_val + ig * ch;
            float tc = 2.f / (1.f + __expf(-2.f * c_val)) - 1.f;
            float hv = og * tc;
            size_t oidx = (size_t)t * BH + (size_t)(bt * 16 + eb) * HDIM + (size_t)jt * 16 + ej;
            out[oidx] = hv;
            if (t == T_STEPS - 1) {
                size_t tail = (size_t)T_STEPS * BH + (size_t)(bt * 16 + eb) * HDIM + (size_t)jt * 16 + ej;
                out[tail]      = hv;      // h_T
                out[tail + BH] = c_val;   // c_T
            }
        }

        // ---- grid-wide barrier (release h_t to all CTAs) ----
        __threadfence();
        __syncthreads();
        if (t < T_STEPS - 1) {
            if (tid == 0) {
                atomicAdd(&g_sync, 1u);
                unsigned target = (unsigned)NCTA_REC * (unsigned)(t + 1);
                while (*reinterpret_cast<volatile unsigned*>(&g_sync) < target) { }
            }
            __syncthreads();
        }
    }
}

// ===========================================================================
extern "C" void kernel_launch(void* const* d_in, const int* in_sizes, int n_in,
                              void* d_out, int out_size)
{
    const float* X   = (const float*)d_in[0];
    const float* Wxf = (const float*)d_in[1];
    const float* Whf = (const float*)d_in[2];
    const float* bf  = (const float*)d_in[3];
    const float* Wxi = (const float*)d_in[4];
    const float* Whi = (const float*)d_in[5];
    const float* bi  = (const float*)d_in[6];
    const float* Wxo = (const float*)d_in[7];
    const float* Who = (const float*)d_in[8];
    const float* bo  = (const float*)d_in[9];
    const float* Wxc = (const float*)d_in[10];
    const float* Whc = (const float*)d_in[11];
    const float* bc  = (const float*)d_in[12];
    float* out = (float*)d_out;

    cudaFuncSetAttribute(lstm_rec_kernel,
                         cudaFuncAttributeMaxDynamicSharedMemorySize, REC_SMEM);

    reset_kernel<<<1, 1>>>();
    dim3 grid1(GDIM / 128, (T_STEPS * BATCH) / 128);
    xgemm_kernel<<<grid1, 256>>>(X, Wxf, Wxi, Wxo, Wxc, bf, bi, bo, bc);
    lstm_rec_kernel<<<NCTA_REC, 256, REC_SMEM>>>(out, Whf, Whi, Who, Whc);
}

// round 2
// speedup vs baseline: 1.3770x; 1.3770x over previous
#include <cuda_runtime.h>
#include <cstdint>
#include <cstddef>

#define T_STEPS 2048
#define BATCH   64
#define IDIM    512
#define HDIM    512
#define GDIM    2048                 // 4*H, gate order [f|i|o|c]
#define BH      (BATCH * HDIM)       // 32768
#define NCTA_REC 128

// 1 GiB scratch for precomputed input-side gates Xg[t, b, 4H] (fp32, bias folded in)
__device__ float g_Xg[(size_t)T_STEPS * BATCH * GDIM];
// h exchange buffers in exact tf32 A-fragment layout: [parity][bt][32KB]
__device__ unsigned g_hfrag[2][4][8192];
// per-CTA arrival flags, 128B-strided to dodge L2 hash pairing: [bt][jt][pad]
__device__ unsigned g_flags[4][32][32];

__device__ __forceinline__ unsigned f2tf32(float x) {
    unsigned r;
    asm("cvt.rna.tf32.f32 %0, %1;" : "=r"(r) : "f"(x));
    return r;
}
__device__ __forceinline__ float tanh_f(float x) {
    float y;
    asm("tanh.approx.f32 %0, %1;" : "=f"(y) : "f"(x));
    return y;
}
__device__ __forceinline__ unsigned ld_acq(const unsigned* p) {
    unsigned v;
    asm volatile("ld.global.acquire.gpu.u32 %0, [%1];" : "=r"(v) : "l"(p) : "memory");
    return v;
}
__device__ __forceinline__ void st_rel(unsigned* p, unsigned v) {
    asm volatile("st.global.release.gpu.u32 [%0], %1;" :: "l"(p), "r"(v) : "memory");
}

__device__ __forceinline__ void mma_tf32(float &d0, float &d1, float &d2, float &d3,
                                         unsigned a0, unsigned a1, unsigned a2, unsigned a3,
                                         unsigned b0, unsigned b1) {
    asm volatile(
        "mma.sync.aligned.m16n8k8.row.col.f32.tf32.tf32.f32 "
        "{%0,%1,%2,%3}, {%4,%5,%6,%7}, {%8,%9}, {%0,%1,%2,%3};\n"
        : "+f"(d0), "+f"(d1), "+f"(d2), "+f"(d3)
        : "r"(a0), "r"(a1), "r"(a2), "r"(a3), "r"(b0), "r"(b1));
}

// ===========================================================================
// Phase 1: Xg = X @ Wx + b   ([131072 x 512] @ [512 x 2048], tf32 mma)
// CTA tile 128x128, K-chunk 32, double-buffered smem (dynamic).
// CTA(0,0) also zeroes the recurrence flags (rec launches strictly after).
// ===========================================================================
#define XG_SMEM (2 * 9216 * 4)   // 2 buffers x (As 4608 + Bs 4608) words

__device__ __forceinline__ void xg_ld(const float* __restrict__ X,
                                      const float* __restrict__ Wx,
                                      int m0, int col0, int k0, int tid,
                                      float4 fa[4], float4 fb[4])
{
    #pragma unroll
    for (int i = 0; i < 4; i++) {
        int idx = tid + i * 256;
        int r = idx >> 3;
        int c = (idx & 7) * 4;
        fa[i] = *reinterpret_cast<const float4*>(X + (size_t)(m0 + r) * IDIM + k0 + c);
    }
    #pragma unroll
    for (int i = 0; i < 4; i++) {
        int idx = tid + i * 256;
        int kr = idx >> 5;
        int nf = (idx & 31) * 4;
        fb[i] = *reinterpret_cast<const float4*>(Wx + (size_t)(k0 + kr) * HDIM + col0 + nf);
    }
}

__device__ __forceinline__ void xg_st(unsigned* As, unsigned* Bs, int tid,
                                      const float4 fa[4], const float4 fb[4])
{
    #pragma unroll
    for (int i = 0; i < 4; i++) {
        int idx = tid + i * 256;
        int r = idx >> 3;
        int c = (idx & 7) * 4;
        As[r * 36 + c + 0] = f2tf32(fa[i].x);
        As[r * 36 + c + 1] = f2tf32(fa[i].y);
        As[r * 36 + c + 2] = f2tf32(fa[i].z);
        As[r * 36 + c + 3] = f2tf32(fa[i].w);
    }
    #pragma unroll
    for (int i = 0; i < 4; i++) {
        int idx = tid + i * 256;
        int kr = idx >> 5;
        int nf = (idx & 31) * 4;
        Bs[(nf + 0) * 36 + kr] = f2tf32(fb[i].x);
        Bs[(nf + 1) * 36 + kr] = f2tf32(fb[i].y);
        Bs[(nf + 2) * 36 + kr] = f2tf32(fb[i].z);
        Bs[(nf + 3) * 36 + kr] = f2tf32(fb[i].w);
    }
}

__global__ void __launch_bounds__(256, 2) xgemm_kernel(
    const float* __restrict__ X,
    const float* __restrict__ Wxf, const float* __restrict__ Wxi,
    const float* __restrict__ Wxo, const float* __restrict__ Wxc,
    const float* __restrict__ bf, const float* __restrict__ bi,
    const float* __restrict__ bo, const float* __restrict__ bc)
{
    extern __shared__ unsigned xsm[];

    const int tid  = threadIdx.x;
    const int warp = tid >> 5;
    const int lane = tid & 31;
    const int m0 = blockIdx.y * 128;
    const int n0 = blockIdx.x * 128;
    const int wm = (warp >> 2) * 64;    // warp grid 2(M) x 4(N), warp tile 64x32
    const int wn = (warp & 3) * 32;

    // reset recurrence flags (rec kernel runs after this kernel completes)
    if (blockIdx.x == 0 && blockIdx.y == 0) {
        unsigned* f = reinterpret_cast<unsigned*>(g_flags);
        for (int i = tid; i < 4 * 32 * 32; i += 256) f[i] = 0u;
    }

    const int g    = n0 >> 9;           // gate for this CTA (uniform)
    const int col0 = n0 & 511;
    const float* Wx = (g == 0) ? Wxf : (g == 1) ? Wxi : (g == 2) ? Wxo : Wxc;
    const float* bb = (g == 0) ? bf  : (g == 1) ? bi  : (g == 2) ? bo  : bc;

    float acc[4][4][4];
    #pragma unroll
    for (int mt = 0; mt < 4; mt++)
        #pragma unroll
        for (int nt = 0; nt < 4; nt++)
            #pragma unroll
            for (int e = 0; e < 4; e++) acc[mt][nt][e] = 0.f;

    // prologue: chunk 0 -> buffer 0
    {
        float4 fa[4], fb[4];
        xg_ld(X, Wx, m0, col0, 0, tid, fa, fb);
        xg_st(xsm, xsm + 4608, tid, fa, fb);
    }
    __syncthreads();

    #pragma unroll 1
    for (int kc = 0; kc < 16; kc++) {
        const int cur = kc & 1;
        unsigned* As = xsm + cur * 9216;
        unsigned* Bs = xsm + cur * 9216 + 4608;

        float4 fa[4], fb[4];
        if (kc < 15) xg_ld(X, Wx, m0, col0, (kc + 1) * 32, tid, fa, fb);

        #pragma unroll
        for (int kk = 0; kk < 32; kk += 8) {
            unsigned a[4][4], b[4][2];
            const int kcol = kk + (lane & 3);
            #pragma unroll
            for (int mt = 0; mt < 4; mt++) {
                int r = wm + mt * 16 + (lane >> 2);
                a[mt][0] = As[r * 36 + kcol];
                a[mt][1] = As[(r + 8) * 36 + kcol];
                a[mt][2] = As[r * 36 + kcol + 4];
                a[mt][3] = As[(r + 8) * 36 + kcol + 4];
            }
            #pragma unroll
            for (int nt = 0; nt < 4; nt++) {
                int n = wn + nt * 8 + (lane >> 2);
                b[nt][0] = Bs[n * 36 + kcol];
                b[nt][1] = Bs[n * 36 + kcol + 4];
            }
            #pragma unroll
            for (int mt = 0; mt < 4; mt++)
                #pragma unroll
                for (int nt = 0; nt < 4; nt++)
                    mma_tf32(acc[mt][nt][0], acc[mt][nt][1], acc[mt][nt][2], acc[mt][nt][3],
                             a[mt][0], a[mt][1], a[mt][2], a[mt][3],
                             b[nt][0], b[nt][1]);
        }

        if (kc < 15) {
            unsigned* An = xsm + (cur ^ 1) * 9216;
            xg_st(An, An + 4608, tid, fa, fb);
        }
        __syncthreads();
    }

    // epilogue: + bias, fp32 store
    #pragma unroll
    for (int mt = 0; mt < 4; mt++) {
        #pragma unroll
        for (int nt = 0; nt < 4; nt++) {
            int nloc = wn + nt * 8 + (lane & 3) * 2;
            int r = m0 + wm + mt * 16 + (lane >> 2);
            float bv0 = bb[col0 + nloc];
            float bv1 = bb[col0 + nloc + 1];
            float2 v0 = make_float2(acc[mt][nt][0] + bv0, acc[mt][nt][1] + bv1);
            float2 v1 = make_float2(acc[mt][nt][2] + bv0, acc[mt][nt][3] + bv1);
            *reinterpret_cast<float2*>(&g_Xg[(size_t)r * GDIM + n0 + nloc]) = v0;
            *reinterpret_cast<float2*>(&g_Xg[(size_t)(r + 8) * GDIM + n0 + nloc]) = v1;
        }
    }
}

// ===========================================================================
// Phase 2: persistent recurrence. 128 CTAs = 4 independent groups (batch tile)
// x 32 hidden tiles. Exchange protocol per step:
//   cell writes h in tf32 A-fragment layout to g_hfrag[t&1][bt] (1 STG.32/thr)
//   __syncthreads; tid0: fence.gpu (cumulative) + release-store flag = t+1
//   32 threads acquire-poll the group's 32 flags; __syncthreads
//   next step: coalesced 32KB __ldcg copy g_hfrag -> smem, mma directly.
// ===========================================================================
#define REC_SMEM (131072 + 32768 + 16 * 66 * 4)   // Wfrag + hfrag + gate staging

__global__ void __launch_bounds__(256, 1) lstm_rec_kernel(
    float* __restrict__ out,
    const float* __restrict__ Whf, const float* __restrict__ Whi,
    const float* __restrict__ Who, const float* __restrict__ Whc)
{
    extern __shared__ unsigned char smem_raw[];
    uint2* Wfrag = reinterpret_cast<uint2*>(smem_raw);                   // [8 warps][64 ki][32 lanes]
    uint4* hfrag = reinterpret_cast<uint4*>(smem_raw + 131072);          // [64 ki][32 lanes]
    float* gs    = reinterpret_cast<float*>(smem_raw + 131072 + 32768);  // [16][66]

    const int tid  = threadIdx.x;
    const int warp = tid >> 5;
    const int lane = tid & 31;
    const int bt = blockIdx.x >> 5;   // batch group 0..3  (16 rows)
    const int jt = blockIdx.x & 31;   // hidden tile 0..31 (16 cols)

    // ---- one-time W_h fragment pre-swizzle (per warp: its 8 gate-cols) ----
    {
        const int gg = warp >> 1;     // gate of this warp's 8-col slice (uniform)
        const float* Wh = (gg == 0) ? Whf : (gg == 1) ? Whi : (gg == 2) ? Who : Whc;
        const int n   = warp * 8 + (lane >> 2);   // CTA gate col 0..63
        const int col = jt * 16 + (n & 15);
        const int kb  = lane & 3;
        #pragma unroll 4
        for (int ki = 0; ki < 64; ki++) {
            int k = ki * 8 + kb;
            unsigned w0 = f2tf32(Wh[(size_t)k * HDIM + col]);
            unsigned w1 = f2tf32(Wh[(size_t)(k + 4) * HDIM + col]);
            Wfrag[(warp * 64 + ki) * 32 + lane] = make_uint2(w0, w1);
        }
    }

    // elementwise mapping: one thread owns cell state c[bt*16+eb][jt*16+ej]
    const int eb = tid >> 4;
    const int ej = tid & 15;
    float c_val = 0.f;

    // producer scatter coordinates (tf32 A-fragment position of h[eb][jt*16+ej])
    const int kcol = jt * 16 + ej;
    const int p_idx = (((kcol >> 3) * 32) + (((eb & 7) << 2) | (kcol & 3))) * 4
                      + ((eb >> 3) | ((kcol & 4) >> 1));

    // D-fragment coordinates for this thread
    const int r     = lane >> 2;                      // 0..7
    const int cpair = warp * 8 + ((lane & 3) << 1);   // even gate-col 0..62
    const size_t xg_col = (size_t)(cpair >> 4) * HDIM + (size_t)jt * 16 + (cpair & 15);

    // Xg prefetch for t = 0
    float2 nx0, nx1;
    {
        size_t rb = (size_t)bt * 16 * GDIM;
        nx0 = *reinterpret_cast<const float2*>(&g_Xg[rb + (size_t)r * GDIM + xg_col]);
        nx1 = *reinterpret_cast<const float2*>(&g_Xg[rb + (size_t)(r + 8) * GDIM + xg_col]);
    }

    __syncthreads();

    #pragma unroll 1
    for (int t = 0; t < T_STEPS; t++) {
        // ---- bring h_{t-1} fragments into smem ----
        if (t == 0) {
            #pragma unroll
            for (int i = 0; i < 8; i++)
                hfrag[tid + i * 256] = make_uint4(0u, 0u, 0u, 0u);
        } else {
            const uint4* src = reinterpret_cast<const uint4*>(g_hfrag[(t - 1) & 1][bt]);
            #pragma unroll
            for (int i = 0; i < 8; i++)
                hfrag[tid + i * 256] = __ldcg(src + tid + i * 256);
        }

        // ---- accumulators from prefetched Xg (bias folded in phase 1) ----
        float d0 = nx0.x, d1 = nx0.y, d2 = nx1.x, d3 = nx1.y;

        __syncthreads();   // hfrag ready

        // ---- K=512 mma loop: 64 x (LDS.128 + LDS.64 + HMMA.tf32) ----
        {
            const uint4* hp = hfrag + lane;
            const uint2* wp = reinterpret_cast<const uint2*>(Wfrag) + warp * 2048 + lane;
            #pragma unroll
            for (int ki = 0; ki < 64; ki++) {
                uint4 a = hp[ki * 32];
                uint2 b = wp[ki * 32];
                mma_tf32(d0, d1, d2, d3, a.x, a.y, a.z, a.w, b.x, b.y);
            }
        }

        // ---- gate staging for cross-warp combine ----
        *reinterpret_cast<float2*>(&gs[r * 66 + cpair])       = make_float2(d0, d1);
        *reinterpret_cast<float2*>(&gs[(r + 8) * 66 + cpair]) = make_float2(d2, d3);
        __syncthreads();

        // ---- LSTM cell (one (b,j) per thread) ----
        float hv;
        {
            float gf = gs[eb * 66 +  0 + ej];
            float gi = gs[eb * 66 + 16 + ej];
            float go = gs[eb * 66 + 32 + ej];
            float gc = gs[eb * 66 + 48 + ej];
            float fg = 0.5f * tanh_f(0.5f * gf) + 0.5f;
            float ig = 0.5f * tanh_f(0.5f * gi) + 0.5f;
            float og = 0.5f * tanh_f(0.5f * go) + 0.5f;
            float ch = tanh_f(gc);
            c_val = fg * c_val + ig * ch;
            hv = og * tanh_f(c_val);
        }

        // ---- publish h_t fragment, release flag ----
        g_hfrag[t & 1][bt][p_idx] = f2tf32(hv);
        __syncthreads();          // all fragment stores issued
        if (tid == 0) {
            __threadfence();      // cumulative gpu fence (covers whole CTA via bar)
            st_rel(&g_flags[bt][jt][0], (unsigned)(t + 1));
        }

        // ---- plain h output (off critical path) ----
        size_t oidx = (size_t)t * BH + (size_t)(bt * 16 + eb) * HDIM + (size_t)jt * 16 + ej;
        out[oidx] = hv;
        if (t == T_STEPS - 1) {
            size_t tail = (size_t)T_STEPS * BH + (size_t)(bt * 16 + eb) * HDIM + (size_t)jt * 16 + ej;
            out[tail]      = hv;      // h_T
            out[tail + BH] = c_val;   // c_T
        }

        // ---- prefetch Xg for t+1 (overlaps the flag poll) ----
        if (t + 1 < T_STEPS) {
            size_t rb = ((size_t)(t + 1) * BATCH + (size_t)bt * 16) * (size_t)GDIM;
            nx0 = *reinterpret_cast<const float2*>(&g_Xg[rb + (size_t)r * GDIM + xg_col]);
            nx1 = *reinterpret_cast<const float2*>(&g_Xg[rb + (size_t)(r + 8) * GDIM + xg_col]);

            // ---- group barrier: wait for all 32 CTAs of this batch group ----
            if (tid < 32) {
                const unsigned* fp = &g_flags[bt][tid][0];
                while (ld_acq(fp) < (unsigned)(t + 1)) { }
            }
            __syncthreads();
        }
    }
}

// ===========================================================================
extern "C" void kernel_launch(void* const* d_in, const int* in_sizes, int n_in,
                              void* d_out, int out_size)
{
    const float* X   = (const float*)d_in[0];
    const float* Wxf = (const float*)d_in[1];
    const float* Whf = (const float*)d_in[2];
    const float* bf  = (const float*)d_in[3];
    const float* Wxi = (const float*)d_in[4];
    const float* Whi = (const float*)d_in[5];
    const float* bi  = (const float*)d_in[6];
    const float* Wxo = (const float*)d_in[7];
    const float* Who = (const float*)d_in[8];
    const float* bo  = (const float*)d_in[9];
    const float* Wxc = (const float*)d_in[10];
    const float* Whc = (const float*)d_in[11];
    const float* bc  = (const float*)d_in[12];
    float* out = (float*)d_out;

    cudaFuncSetAttribute(xgemm_kernel,
                         cudaFuncAttributeMaxDynamicSharedMemorySize, XG_SMEM);
    cudaFuncSetAttribute(lstm_rec_kernel,
                         cudaFuncAttributeMaxDynamicSharedMemorySize, REC_SMEM);

    dim3 grid1(GDIM / 128, (T_STEPS * BATCH) / 128);
    xgemm_kernel<<<grid1, 256, XG_SMEM>>>(X, Wxf, Wxi, Wxo, Wxc, bf, bi, bo, bc);
    lstm_rec_kernel<<<NCTA_REC, 256, REC_SMEM>>>(out, Whf, Whi, Who, Whc);
}

// round 5
// speedup vs baseline: 2.2731x; 1.6507x over previous
#include <cuda_runtime.h>
#include <cstdint>
#include <cstddef>

#define T_STEPS 2048
#define BATCH   64
#define IDIM    512
#define HDIM    512
#define GDIM    2048                 // 4*H, gate order [f|i|o|c]
#define BH      (BATCH * HDIM)       // 32768
#define NCTA_REC 128

// 1 GiB scratch for precomputed input-side gates Xg[t, b, 4H] (fp32, bias folded in)
__device__ float g_Xg[(size_t)T_STEPS * BATCH * GDIM];
// h exchange buffers in exact tf32 B-fragment layout: [parity][group][8192 words]
__device__ unsigned g_hfrag[2][4][8192];
// per-CTA arrival flags, 128B-strided: [group][jt][pad]
__device__ unsigned g_flags[4][32][32];

__device__ __forceinline__ unsigned f2tf32(float x) {
    unsigned r;
    asm("cvt.rna.tf32.f32 %0, %1;" : "=r"(r) : "f"(x));
    return r;
}
__device__ __forceinline__ float tanh_f(float x) {
    float y;
    asm("tanh.approx.f32 %0, %1;" : "=f"(y) : "f"(x));
    return y;
}
__device__ __forceinline__ unsigned ld_acq(const unsigned* p) {
    unsigned v;
    asm volatile("ld.global.acquire.gpu.u32 %0, [%1];" : "=r"(v) : "l"(p) : "memory");
    return v;
}
__device__ __forceinline__ void st_rel(unsigned* p, unsigned v) {
    asm volatile("st.global.release.gpu.u32 [%0], %1;" :: "l"(p), "r"(v) : "memory");
}

__device__ __forceinline__ void mma_tf32(float &d0, float &d1, float &d2, float &d3,
                                         unsigned a0, unsigned a1, unsigned a2, unsigned a3,
                                         unsigned b0, unsigned b1) {
    asm volatile(
        "mma.sync.aligned.m16n8k8.row.col.f32.tf32.tf32.f32 "
        "{%0,%1,%2,%3}, {%4,%5,%6,%7}, {%8,%9}, {%0,%1,%2,%3};\n"
        : "+f"(d0), "+f"(d1), "+f"(d2), "+f"(d3)
        : "r"(a0), "r"(a1), "r"(a2), "r"(a3), "r"(b0), "r"(b1));
}

// ===========================================================================
// Phase 1: Xg = X @ Wx + b   ([131072 x 512] @ [512 x 2048], tf32 mma)
// CTA tile 128x128, K-chunk 32, double-buffered smem.
// ===========================================================================
#define XG_SMEM (2 * 9216 * 4)

__device__ __forceinline__ void xg_ld(const float* __restrict__ X,
                                      const float* __restrict__ Wx,
                                      int m0, int col0, int k0, int tid,
                                      float4 fa[4], float4 fb[4])
{
    #pragma unroll
    for (int i = 0; i < 4; i++) {
        int idx = tid + i * 256;
        int r = idx >> 3;
        int c = (idx & 7) * 4;
        fa[i] = *reinterpret_cast<const float4*>(X + (size_t)(m0 + r) * IDIM + k0 + c);
    }
    #pragma unroll
    for (int i = 0; i < 4; i++) {
        int idx = tid + i * 256;
        int kr = idx >> 5;
        int nf = (idx & 31) * 4;
        fb[i] = *reinterpret_cast<const float4*>(Wx + (size_t)(k0 + kr) * HDIM + col0 + nf);
    }
}

__device__ __forceinline__ void xg_st(unsigned* As, unsigned* Bs, int tid,
                                      const float4 fa[4], const float4 fb[4])
{
    #pragma unroll
    for (int i = 0; i < 4; i++) {
        int idx = tid + i * 256;
        int r = idx >> 3;
        int c = (idx & 7) * 4;
        As[r * 36 + c + 0] = f2tf32(fa[i].x);
        As[r * 36 + c + 1] = f2tf32(fa[i].y);
        As[r * 36 + c + 2] = f2tf32(fa[i].z);
        As[r * 36 + c + 3] = f2tf32(fa[i].w);
    }
    #pragma unroll
    for (int i = 0; i < 4; i++) {
        int idx = tid + i * 256;
        int kr = idx >> 5;
        int nf = (idx & 31) * 4;
        Bs[(nf + 0) * 36 + kr] = f2tf32(fb[i].x);
        Bs[(nf + 1) * 36 + kr] = f2tf32(fb[i].y);
        Bs[(nf + 2) * 36 + kr] = f2tf32(fb[i].z);
        Bs[(nf + 3) * 36 + kr] = f2tf32(fb[i].w);
    }
}

__global__ void __launch_bounds__(256, 2) xgemm_kernel(
    const float* __restrict__ X,
    const float* __restrict__ Wxf, const float* __restrict__ Wxi,
    const float* __restrict__ Wxo, const float* __restrict__ Wxc,
    const float* __restrict__ bf, const float* __restrict__ bi,
    const float* __restrict__ bo, const float* __restrict__ bc)
{
    extern __shared__ unsigned xsm[];

    const int tid  = threadIdx.x;
    const int warp = tid >> 5;
    const int lane = tid & 31;
    const int m0 = blockIdx.y * 128;
    const int n0 = blockIdx.x * 128;
    const int wm = (warp >> 2) * 64;
    const int wn = (warp & 3) * 32;

    if (blockIdx.x == 0 && blockIdx.y == 0) {
        unsigned* f = reinterpret_cast<unsigned*>(g_flags);
        for (int i = tid; i < 4 * 32 * 32; i += 256) f[i] = 0u;
    }

    const int g    = n0 >> 9;
    const int col0 = n0 & 511;
    const float* Wx = (g == 0) ? Wxf : (g == 1) ? Wxi : (g == 2) ? Wxo : Wxc;
    const float* bb = (g == 0) ? bf  : (g == 1) ? bi  : (g == 2) ? bo  : bc;

    float acc[4][4][4];
    #pragma unroll
    for (int mt = 0; mt < 4; mt++)
        #pragma unroll
        for (int nt = 0; nt < 4; nt++)
            #pragma unroll
            for (int e = 0; e < 4; e++) acc[mt][nt][e] = 0.f;

    {
        float4 fa[4], fb[4];
        xg_ld(X, Wx, m0, col0, 0, tid, fa, fb);
        xg_st(xsm, xsm + 4608, tid, fa, fb);
    }
    __syncthreads();

    #pragma unroll 1
    for (int kc = 0; kc < 16; kc++) {
        const int cur = kc & 1;
        unsigned* As = xsm + cur * 9216;
        unsigned* Bs = xsm + cur * 9216 + 4608;

        float4 fa[4], fb[4];
        if (kc < 15) xg_ld(X, Wx, m0, col0, (kc + 1) * 32, tid, fa, fb);

        #pragma unroll
        for (int kk = 0; kk < 32; kk += 8) {
            unsigned a[4][4], b[4][2];
            const int kcol = kk + (lane & 3);
            #pragma unroll
            for (int mt = 0; mt < 4; mt++) {
                int r = wm + mt * 16 + (lane >> 2);
                a[mt][0] = As[r * 36 + kcol];
                a[mt][1] = As[(r + 8) * 36 + kcol];
                a[mt][2] = As[r * 36 + kcol + 4];
                a[mt][3] = As[(r + 8) * 36 + kcol + 4];
            }
            #pragma unroll
            for (int nt = 0; nt < 4; nt++) {
                int n = wn + nt * 8 + (lane >> 2);
                b[nt][0] = Bs[n * 36 + kcol];
                b[nt][1] = Bs[n * 36 + kcol + 4];
            }
            #pragma unroll
            for (int mt = 0; mt < 4; mt++)
                #pragma unroll
                for (int nt = 0; nt < 4; nt++)
                    mma_tf32(acc[mt][nt][0], acc[mt][nt][1], acc[mt][nt][2], acc[mt][nt][3],
                             a[mt][0], a[mt][1], a[mt][2], a[mt][3],
                             b[nt][0], b[nt][1]);
        }

        if (kc < 15) {
            unsigned* An = xsm + (cur ^ 1) * 9216;
            xg_st(An, An + 4608, tid, fa, fb);
        }
        __syncthreads();
    }

    #pragma unroll
    for (int mt = 0; mt < 4; mt++) {
        #pragma unroll
        for (int nt = 0; nt < 4; nt++) {
            int nloc = wn + nt * 8 + (lane & 3) * 2;
            int r = m0 + wm + mt * 16 + (lane >> 2);
            float bv0 = bb[col0 + nloc];
            float bv1 = bb[col0 + nloc + 1];
            float2 v0 = make_float2(acc[mt][nt][0] + bv0, acc[mt][nt][1] + bv1);
            float2 v1 = make_float2(acc[mt][nt][2] + bv0, acc[mt][nt][3] + bv1);
            *reinterpret_cast<float2*>(&g_Xg[(size_t)r * GDIM + n0 + nloc]) = v0;
            *reinterpret_cast<float2*>(&g_Xg[(size_t)(r + 8) * GDIM + n0 + nloc]) = v1;
        }
    }
}

// ===========================================================================
// Phase 2: persistent recurrence. 128 CTAs = 4 groups x 32 hidden tiles,
// 512 threads = 16 warps = 4 gate-tiles(M) x 4 K-splits.
// W_h held ENTIRELY in registers (A operand, 64 regs/thread).
// h (B operand) staged once per step into smem in exact B-frag layout:
// inner loop = 1 LDS.128 + 2 HMMA per ki (131KB smem traffic/step, was 393KB).
// ===========================================================================
#define REC_THREADS 512
#define REC_SMEM (32768 + 256 * 18 * 4)   // hsm (B-frags) + partial-sum buffer

__global__ void __launch_bounds__(512, 1) lstm_rec_kernel(
    float* __restrict__ out,
    const float* __restrict__ Whf, const float* __restrict__ Whi,
    const float* __restrict__ Who, const float* __restrict__ Whc)
{
    extern __shared__ unsigned char smem_raw[];
    uint4* hsm = reinterpret_cast<uint4*>(smem_raw);           // [64 ki][32 lanes] uint4
    float* gs2 = reinterpret_cast<float*>(smem_raw + 32768);   // [16 warps*16 rows][18]

    const int tid  = threadIdx.x;
    const int warp = tid >> 5;
    const int lane = tid & 31;
    const int bt = blockIdx.x >> 5;   // batch group 0..3 (16 rows)
    const int jt = blockIdx.x & 31;   // hidden tile 0..31 (16 cols)

    const int mt = warp >> 2;         // gate 0..3 (warp = mt*4+ks)
    const int ks = warp & 3;          // K chunk 0..3 (128 each)

    // ---- one-time: W_h A-fragments into registers ----
    unsigned Wr[16][4];
    {
        const float* Wh = (mt == 0) ? Whf : (mt == 1) ? Whi : (mt == 2) ? Who : Whc;
        const int colA = jt * 16 + (lane >> 2);
        #pragma unroll
        for (int ki = 0; ki < 16; ki++) {
            int k = ks * 128 + ki * 8 + (lane & 3);
            Wr[ki][0] = f2tf32(Wh[(size_t)k * HDIM + colA]);
            Wr[ki][1] = f2tf32(Wh[(size_t)k * HDIM + colA + 8]);
            Wr[ki][2] = f2tf32(Wh[(size_t)(k + 4) * HDIM + colA]);
            Wr[ki][3] = f2tf32(Wh[(size_t)(k + 4) * HDIM + colA + 8]);
        }
    }

    // cell thread mapping (tid < 256): owns c[bt*16+eb][jt*16+ej]
    const int eb = tid >> 4;          // 0..15 (tid<256)
    const int ej = tid & 15;
    float c_val = 0.f;

    // publisher position of h[eb][jt*16+ej] in B-frag layout
    const int jg = jt * 16 + ej;
    const int p_idx = (((jg >> 3) * 32) + (((eb & 7) << 2) | (jg & 3))) * 4
                      + (((eb >> 3) << 1) | ((jg >> 2) & 1));

    // Xg prefetch for t=0 (tid < 256)
    float xgv[4];
    if (tid < 256) {
        size_t xb = ((size_t)bt * 16 + eb) * GDIM + jt * 16 + ej;
        #pragma unroll
        for (int g = 0; g < 4; g++) xgv[g] = g_Xg[xb + g * HDIM];
    }

    // zero h for t=0
    #pragma unroll
    for (int i = 0; i < 4; i++)
        hsm[tid + i * 512] = make_uint4(0u, 0u, 0u, 0u);
    __syncthreads();

    #pragma unroll 1
    for (int t = 0; t < T_STEPS; t++) {
        if (t > 0) {
            const uint4* src = reinterpret_cast<const uint4*>(g_hfrag[(t - 1) & 1][bt]);
            #pragma unroll
            for (int i = 0; i < 4; i++)
                hsm[tid + i * 512] = __ldcg(src + tid + i * 512);
            __syncthreads();
        }

        // ---- 16 ki: 1 LDS.128 + 2 HMMA (two interleaved acc chains) ----
        float a0[4] = {0.f, 0.f, 0.f, 0.f};
        float a1[4] = {0.f, 0.f, 0.f, 0.f};
        {
            const uint4* hp = hsm + ks * 512 + lane;
            #pragma unroll
            for (int ki = 0; ki < 16; ki++) {
                uint4 hb = hp[ki * 32];
                mma_tf32(a0[0], a0[1], a0[2], a0[3],
                         Wr[ki][0], Wr[ki][1], Wr[ki][2], Wr[ki][3], hb.x, hb.y);
                mma_tf32(a1[0], a1[1], a1[2], a1[3],
                         Wr[ki][0], Wr[ki][1], Wr[ki][2], Wr[ki][3], hb.z, hb.w);
            }
        }

        // ---- write K-partials: rows = gate-col, cols = batch ----
        {
            float* gw = gs2 + (warp * 16) * 18;
            int r  = lane >> 2;
            int c2 = (lane & 3) * 2;
            *reinterpret_cast<float2*>(&gw[r * 18 + c2])           = make_float2(a0[0], a0[1]);
            *reinterpret_cast<float2*>(&gw[(r + 8) * 18 + c2])     = make_float2(a0[2], a0[3]);
            *reinterpret_cast<float2*>(&gw[r * 18 + 8 + c2])       = make_float2(a1[0], a1[1]);
            *reinterpret_cast<float2*>(&gw[(r + 8) * 18 + 8 + c2]) = make_float2(a1[2], a1[3]);
        }
        __syncthreads();

        // ---- cell: reduce 4 K-partials per gate, apply LSTM nonlinearity ----
        float hv = 0.f;
        if (tid < 256) {
            float gate[4];
            #pragma unroll
            for (int g = 0; g < 4; g++) {
                float s = xgv[g];
                #pragma unroll
                for (int k = 0; k < 4; k++)
                    s += gs2[((g * 4 + k) * 16 + ej) * 18 + eb];
                gate[g] = s;
            }
            float fg = 0.5f * tanh_f(0.5f * gate[0]) + 0.5f;
            float ig = 0.5f * tanh_f(0.5f * gate[1]) + 0.5f;
            float og = 0.5f * tanh_f(0.5f * gate[2]) + 0.5f;
            float ch = tanh_f(gate[3]);
            c_val = fg * c_val + ig * ch;
            hv = og * tanh_f(c_val);

            // publish h_t fragment word
            g_hfrag[t & 1][bt][p_idx] = f2tf32(hv);
        }
        __syncthreads();             // publish stores issued CTA-wide

        if (tid == 0) {
            __threadfence();         // cumulative gpu fence
            st_rel(&g_flags[bt][jt][0], (unsigned)(t + 1));
        }

        // ---- off-critical-path output + next-step Xg prefetch ----
        if (tid < 256) {
            size_t oidx = (size_t)t * BH + (size_t)(bt * 16 + eb) * HDIM + (size_t)jt * 16 + ej;
            out[oidx] = hv;
            if (t == T_STEPS - 1) {
                size_t tail = (size_t)T_STEPS * BH + (size_t)(bt * 16 + eb) * HDIM + (size_t)jt * 16 + ej;
                out[tail]      = hv;      // h_T
                out[tail + BH] = c_val;   // c_T
            }
            if (t + 1 < T_STEPS) {
                size_t xb = ((size_t)(t + 1) * BATCH + (size_t)bt * 16 + eb) * GDIM + jt * 16 + ej;
                #pragma unroll
                for (int g = 0; g < 4; g++) xgv[g] = g_Xg[xb + g * HDIM];
            }
        }

        // ---- group barrier (32 CTAs of this batch group) ----
        if (t + 1 < T_STEPS) {
            if (tid < 32) {
                const unsigned* fp = &g_flags[bt][tid][0];
                while (ld_acq(fp) < (unsigned)(t + 1)) { }
            }
            __syncthreads();
        }
    }
}

// ===========================================================================
extern "C" void kernel_launch(void* const* d_in, const int* in_sizes, int n_in,
                              void* d_out, int out_size)
{
    const float* X   = (const float*)d_in[0];
    const float* Wxf = (const float*)d_in[1];
    const float* Whf = (const float*)d_in[2];
    const float* bf  = (const float*)d_in[3];
    const float* Wxi = (const float*)d_in[4];
    const float* Whi = (const float*)d_in[5];
    const float* bi  = (const float*)d_in[6];
    const float* Wxo = (const float*)d_in[7];
    const float* Who = (const float*)d_in[8];
    const float* bo  = (const float*)d_in[9];
    const float* Wxc = (const float*)d_in[10];
    const float* Whc = (const float*)d_in[11];
    const float* bc  = (const float*)d_in[12];
    float* out = (float*)d_out;

    cudaFuncSetAttribute(xgemm_kernel,
                         cudaFuncAttributeMaxDynamicSharedMemorySize, XG_SMEM);
    cudaFuncSetAttribute(lstm_rec_kernel,
                         cudaFuncAttributeMaxDynamicSharedMemorySize, REC_SMEM);

    dim3 grid1(GDIM / 128, (T_STEPS * BATCH) / 128);
    xgemm_kernel<<<grid1, 256, XG_SMEM>>>(X, Wxf, Wxi, Wxo, Wxc, bf, bi, bo, bc);
    lstm_rec_kernel<<<NCTA_REC, REC_THREADS, REC_SMEM>>>(out, Whf, Whi, Who, Whc);
}

// round 6
// speedup vs baseline: 2.8961x; 1.2741x over previous
#include <cuda_runtime.h>
#include <cstdint>
#include <cstddef>

#define T_STEPS 2048
#define BATCH   64
#define IDIM    512
#define HDIM    512
#define GDIM    2048                 // 4*H, gate order [f|i|o|c]
#define BH      (BATCH * HDIM)       // 32768
#define NCTA_REC 128

// 1 GiB scratch for precomputed input-side gates Xg[t, b, 4H] (fp32, bias folded in)
__device__ float g_Xg[(size_t)T_STEPS * BATCH * GDIM];
// h exchange buffers in exact tf32 B-fragment layout: [parity][group][8192 words]
__device__ unsigned g_hfrag[2][4][8192];
// per-CTA arrival flags, 128B-strided: [group][jt][pad]
__device__ unsigned g_flags[4][32][32];

__device__ __forceinline__ unsigned f2tf32(float x) {
    unsigned r;
    asm("cvt.rna.tf32.f32 %0, %1;" : "=r"(r) : "f"(x));
    return r;
}
__device__ __forceinline__ float tanh_f(float x) {
    float y;
    asm("tanh.approx.f32 %0, %1;" : "=f"(y) : "f"(x));
    return y;
}
__device__ __forceinline__ unsigned ld_acq(const unsigned* p) {
    unsigned v;
    asm volatile("ld.global.acquire.gpu.u32 %0, [%1];" : "=r"(v) : "l"(p) : "memory");
    return v;
}
__device__ __forceinline__ void st_rel(unsigned* p, unsigned v) {
    asm volatile("st.global.release.gpu.u32 [%0], %1;" :: "l"(p), "r"(v) : "memory");
}
__device__ __forceinline__ void cp16(void* dst_smem, const void* src) {
    unsigned d = (unsigned)__cvta_generic_to_shared(dst_smem);
    asm volatile("cp.async.ca.shared.global [%0], [%1], 16;" :: "r"(d), "l"(src));
}
__device__ __forceinline__ void cp_commit() {
    asm volatile("cp.async.commit_group;");
}
__device__ __forceinline__ void cp_wait0() {
    asm volatile("cp.async.wait_group 0;");
}
__device__ __forceinline__ void cp_wait1() {
    asm volatile("cp.async.wait_group 1;");
}

__device__ __forceinline__ void mma_tf32(float &d0, float &d1, float &d2, float &d3,
                                         unsigned a0, unsigned a1, unsigned a2, unsigned a3,
                                         unsigned b0, unsigned b1) {
    asm volatile(
        "mma.sync.aligned.m16n8k8.row.col.f32.tf32.tf32.f32 "
        "{%0,%1,%2,%3}, {%4,%5,%6,%7}, {%8,%9}, {%0,%1,%2,%3};\n"
        : "+f"(d0), "+f"(d1), "+f"(d2), "+f"(d3)
        : "r"(a0), "r"(a1), "r"(a2), "r"(a3), "r"(b0), "r"(b1));
}

// ===========================================================================
// Phase 1: Xg = X @ Wx + b  ([131072 x 512] @ [512 x 2048])
// cp.async double-buffered; raw fp32 in smem (tf32 mma truncates in HW).
// A smem [m][k] pad 36; B smem [k][n] pad 136 (both conflict-free).
// ===========================================================================
#define XA_STRIDE 36
#define XB_STRIDE 136
#define XA_WORDS (128 * XA_STRIDE)          // 4608
#define XB_WORDS (32 * XB_STRIDE)           // 4352
#define XBUF_WORDS (XA_WORDS + XB_WORDS)    // 8960
#define XG_SMEM (2 * XBUF_WORDS * 4)        // 71680 B

__device__ __forceinline__ void xg_issue(const float* __restrict__ X,
                                         const float* __restrict__ Wx,
                                         int m0, int col0, int k0, int tid,
                                         float* As, float* Bs)
{
    #pragma unroll
    for (int i = 0; i < 4; i++) {
        int idx = tid + i * 256;                 // 1024 float4 slots
        int r = idx >> 3;
        int c4 = (idx & 7) * 4;
        cp16(As + r * XA_STRIDE + c4, X + (size_t)(m0 + r) * IDIM + k0 + c4);
    }
    #pragma unroll
    for (int i = 0; i < 4; i++) {
        int idx = tid + i * 256;
        int kr = idx >> 5;
        int nf = (idx & 31) * 4;
        cp16(Bs + kr * XB_STRIDE + nf, Wx + (size_t)(k0 + kr) * HDIM + col0 + nf);
    }
}

__global__ void __launch_bounds__(256, 2) xgemm_kernel(
    const float* __restrict__ X,
    const float* __restrict__ Wxf, const float* __restrict__ Wxi,
    const float* __restrict__ Wxo, const float* __restrict__ Wxc,
    const float* __restrict__ bf, const float* __restrict__ bi,
    const float* __restrict__ bo, const float* __restrict__ bc)
{
    extern __shared__ float xsm[];

    const int tid  = threadIdx.x;
    const int warp = tid >> 5;
    const int lane = tid & 31;
    const int m0 = blockIdx.y * 128;
    const int n0 = blockIdx.x * 128;
    const int wm = (warp >> 2) * 64;    // warp grid 2(M) x 4(N), warp tile 64x32
    const int wn = (warp & 3) * 32;

    if (blockIdx.x == 0 && blockIdx.y == 0) {
        unsigned* f = reinterpret_cast<unsigned*>(g_flags);
        for (int i = tid; i < 4 * 32 * 32; i += 256) f[i] = 0u;
    }

    const int g    = n0 >> 9;
    const int col0 = n0 & 511;
    const float* Wx = (g == 0) ? Wxf : (g == 1) ? Wxi : (g == 2) ? Wxo : Wxc;
    const float* bb = (g == 0) ? bf  : (g == 1) ? bi  : (g == 2) ? bo  : bc;

    float acc[4][4][4];
    #pragma unroll
    for (int mt = 0; mt < 4; mt++)
        #pragma unroll
        for (int nt = 0; nt < 4; nt++)
            #pragma unroll
            for (int e = 0; e < 4; e++) acc[mt][nt][e] = 0.f;

    // prologue: chunk 0 -> buffer 0
    xg_issue(X, Wx, m0, col0, 0, tid, xsm, xsm + XA_WORDS);
    cp_commit();

    #pragma unroll 1
    for (int kc = 0; kc < 16; kc++) {
        if (kc < 15) {
            float* nb = xsm + ((kc + 1) & 1) * XBUF_WORDS;
            xg_issue(X, Wx, m0, col0, (kc + 1) * 32, tid, nb, nb + XA_WORDS);
            cp_commit();
            cp_wait1();                 // current chunk complete
        } else {
            cp_wait0();
        }
        __syncthreads();

        const unsigned* Au = reinterpret_cast<const unsigned*>(xsm + (kc & 1) * XBUF_WORDS);
        const unsigned* Bu = Au + XA_WORDS;

        #pragma unroll
        for (int kk = 0; kk < 32; kk += 8) {
            unsigned a[4][4], b[4][2];
            const int kcol = kk + (lane & 3);
            #pragma unroll
            for (int mt = 0; mt < 4; mt++) {
                int r = wm + mt * 16 + (lane >> 2);
                a[mt][0] = Au[r * XA_STRIDE + kcol];
                a[mt][1] = Au[(r + 8) * XA_STRIDE + kcol];
                a[mt][2] = Au[r * XA_STRIDE + kcol + 4];
                a[mt][3] = Au[(r + 8) * XA_STRIDE + kcol + 4];
            }
            #pragma unroll
            for (int nt = 0; nt < 4; nt++) {
                int n = wn + nt * 8 + (lane >> 2);
                b[nt][0] = Bu[kcol * XB_STRIDE + n];
                b[nt][1] = Bu[(kcol + 4) * XB_STRIDE + n];
            }
            #pragma unroll
            for (int mt = 0; mt < 4; mt++)
                #pragma unroll
                for (int nt = 0; nt < 4; nt++)
                    mma_tf32(acc[mt][nt][0], acc[mt][nt][1], acc[mt][nt][2], acc[mt][nt][3],
                             a[mt][0], a[mt][1], a[mt][2], a[mt][3],
                             b[nt][0], b[nt][1]);
        }
        __syncthreads();
    }

    // epilogue: + bias, fp32 store
    #pragma unroll
    for (int mt = 0; mt < 4; mt++) {
        #pragma unroll
        for (int nt = 0; nt < 4; nt++) {
            int nloc = wn + nt * 8 + (lane & 3) * 2;
            int r = m0 + wm + mt * 16 + (lane >> 2);
            float bv0 = bb[col0 + nloc];
            float bv1 = bb[col0 + nloc + 1];
            float2 v0 = make_float2(acc[mt][nt][0] + bv0, acc[mt][nt][1] + bv1);
            float2 v1 = make_float2(acc[mt][nt][2] + bv0, acc[mt][nt][3] + bv1);
            *reinterpret_cast<float2*>(&g_Xg[(size_t)r * GDIM + n0 + nloc]) = v0;
            *reinterpret_cast<float2*>(&g_Xg[(size_t)(r + 8) * GDIM + n0 + nloc]) = v1;
        }
    }
}

// ===========================================================================
// Phase 2: persistent recurrence. 128 CTAs = 4 groups x 32 hidden tiles,
// 512 threads = 16 warps = 4 gate-tiles(M) x 4 K-splits.
// W_h in registers; h B-frags staged via smem (1 LDS.128 + 2 HMMA per ki).
// Publish: cell -> smem pub (1KB) -> ONE warp: 16 STG.128 + syncwarp +
// lane0 fence+release  (CTA's h block is contiguous in g_hfrag).
// ===========================================================================
#define REC_THREADS 512
#define REC_SMEM (32768 + 256 * 18 * 4 + 1024)  // hsm + gs2 + pub

__global__ void __launch_bounds__(512, 1) lstm_rec_kernel(
    float* __restrict__ out,
    const float* __restrict__ Whf, const float* __restrict__ Whi,
    const float* __restrict__ Who, const float* __restrict__ Whc)
{
    extern __shared__ unsigned char smem_raw[];
    uint4* hsm = reinterpret_cast<uint4*>(smem_raw);             // [64 ki][32 lanes]
    float* gs2 = reinterpret_cast<float*>(smem_raw + 32768);     // [256][18]
    unsigned* pub = reinterpret_cast<unsigned*>(smem_raw + 32768 + 256 * 18 * 4); // 256 words

    const int tid  = threadIdx.x;
    const int warp = tid >> 5;
    const int lane = tid & 31;
    const int bt = blockIdx.x >> 5;   // batch group 0..3 (16 rows)
    const int jt = blockIdx.x & 31;   // hidden tile 0..31 (16 cols)

    const int mt = warp >> 2;         // gate 0..3
    const int ks = warp & 3;          // K chunk 0..3 (128 each)

    // ---- one-time: W_h A-fragments into registers ----
    unsigned Wr[16][4];
    {
        const float* Wh = (mt == 0) ? Whf : (mt == 1) ? Whi : (mt == 2) ? Who : Whc;
        const int colA = jt * 16 + (lane >> 2);
        #pragma unroll
        for (int ki = 0; ki < 16; ki++) {
            int k = ks * 128 + ki * 8 + (lane & 3);
            Wr[ki][0] = f2tf32(Wh[(size_t)k * HDIM + colA]);
            Wr[ki][1] = f2tf32(Wh[(size_t)k * HDIM + colA + 8]);
            Wr[ki][2] = f2tf32(Wh[(size_t)(k + 4) * HDIM + colA]);
            Wr[ki][3] = f2tf32(Wh[(size_t)(k + 4) * HDIM + colA + 8]);
        }
    }

    // cell thread mapping (tid < 256): owns c[bt*16+eb][jt*16+ej]
    const int eb = tid >> 4;
    const int ej = tid & 15;
    float c_val = 0.f;

    // local (within CTA's contiguous 1KB block) B-frag position of h[eb][ej]
    const int lidx = ((ej >> 3) << 7) + (((eb & 7) << 2) + (ej & 3)) * 4
                     + ((eb >> 3) << 1) + ((ej >> 2) & 1);

    // Xg prefetch for t=0 (tid < 256)
    float xgv[4];
    if (tid < 256) {
        size_t xb = ((size_t)bt * 16 + eb) * GDIM + jt * 16 + ej;
        #pragma unroll
        for (int g = 0; g < 4; g++) xgv[g] = g_Xg[xb + g * HDIM];
    }

    // zero h for t=0
    #pragma unroll
    for (int i = 0; i < 4; i++)
        hsm[tid + i * 512] = make_uint4(0u, 0u, 0u, 0u);
    __syncthreads();

    #pragma unroll 1
    for (int t = 0; t < T_STEPS; t++) {
        if (t > 0) {
            const uint4* src = reinterpret_cast<const uint4*>(g_hfrag[(t - 1) & 1][bt]);
            #pragma unroll
            for (int i = 0; i < 4; i++)
                hsm[tid + i * 512] = __ldcg(src + tid + i * 512);
            __syncthreads();
        }

        // ---- 16 ki: 1 LDS.128 + 2 HMMA (two interleaved acc chains) ----
        float a0[4] = {0.f, 0.f, 0.f, 0.f};
        float a1[4] = {0.f, 0.f, 0.f, 0.f};
        {
            const uint4* hp = hsm + ks * 512 + lane;
            #pragma unroll
            for (int ki = 0; ki < 16; ki++) {
                uint4 hb = hp[ki * 32];
                mma_tf32(a0[0], a0[1], a0[2], a0[3],
                         Wr[ki][0], Wr[ki][1], Wr[ki][2], Wr[ki][3], hb.x, hb.y);
                mma_tf32(a1[0], a1[1], a1[2], a1[3],
                         Wr[ki][0], Wr[ki][1], Wr[ki][2], Wr[ki][3], hb.z, hb.w);
            }
        }

        // ---- write K-partials: rows = gate-col, cols = batch ----
        {
            float* gw = gs2 + (warp * 16) * 18;
            int r  = lane >> 2;
            int c2 = (lane & 3) * 2;
            *reinterpret_cast<float2*>(&gw[r * 18 + c2])           = make_float2(a0[0], a0[1]);
            *reinterpret_cast<float2*>(&gw[(r + 8) * 18 + c2])     = make_float2(a0[2], a0[3]);
            *reinterpret_cast<float2*>(&gw[r * 18 + 8 + c2])       = make_float2(a1[0], a1[1]);
            *reinterpret_cast<float2*>(&gw[(r + 8) * 18 + 8 + c2]) = make_float2(a1[2], a1[3]);
        }
        __syncthreads();

        // ---- cell: reduce 4 K-partials per gate, apply LSTM nonlinearity ----
        float hv = 0.f;
        if (tid < 256) {
            float gate[4];
            #pragma unroll
            for (int g = 0; g < 4; g++) {
                float s = xgv[g];
                #pragma unroll
                for (int k = 0; k < 4; k++)
                    s += gs2[((g * 4 + k) * 16 + ej) * 18 + eb];
                gate[g] = s;
            }
            float fg = 0.5f * tanh_f(0.5f * gate[0]) + 0.5f;
            float ig = 0.5f * tanh_f(0.5f * gate[1]) + 0.5f;
            float og = 0.5f * tanh_f(0.5f * gate[2]) + 0.5f;
            float ch = tanh_f(gate[3]);
            c_val = fg * c_val + ig * ch;
            hv = og * tanh_f(c_val);

            pub[lidx] = f2tf32(hv);      // stage into contiguous block
        }
        __syncthreads();                 // pub ready CTA-wide

        // ---- ONE warp publishes 1KB coalesced + releases flag ----
        if (warp == 0) {
            uint4* dst = reinterpret_cast<uint4*>(&g_hfrag[t & 1][bt][jt * 256]);
            const uint4* ps = reinterpret_cast<const uint4*>(pub);
            dst[lane]      = ps[lane];
            dst[lane + 32] = ps[lane + 32];
            __syncwarp();
            if (lane == 0 && t + 1 < T_STEPS) {
                __threadfence();
                st_rel(&g_flags[bt][jt][0], (unsigned)(t + 1));
            }
        }

        // ---- off-critical-path output + next-step Xg prefetch ----
        if (tid < 256) {
            size_t oidx = (size_t)t * BH + (size_t)(bt * 16 + eb) * HDIM + (size_t)jt * 16 + ej;
            out[oidx] = hv;
            if (t == T_STEPS - 1) {
                size_t tail = (size_t)T_STEPS * BH + (size_t)(bt * 16 + eb) * HDIM + (size_t)jt * 16 + ej;
                out[tail]      = hv;      // h_T
                out[tail + BH] = c_val;   // c_T
            }
            if (t + 1 < T_STEPS) {
                size_t xb = ((size_t)(t + 1) * BATCH + (size_t)bt * 16 + eb) * GDIM + jt * 16 + ej;
                #pragma unroll
                for (int g = 0; g < 4; g++) xgv[g] = g_Xg[xb + g * HDIM];
            }
        }

        // ---- group barrier (32 CTAs of this batch group) ----
        if (t + 1 < T_STEPS) {
            if (tid < 32) {
                const unsigned* fp = &g_flags[bt][tid][0];
                while (ld_acq(fp) < (unsigned)(t + 1)) { }
            }
            __syncthreads();
        }
    }
}

// ===========================================================================
extern "C" void kernel_launch(void* const* d_in, const int* in_sizes, int n_in,
                              void* d_out, int out_size)
{
    const float* X   = (const float*)d_in[0];
    const float* Wxf = (const float*)d_in[1];
    const float* Whf = (const float*)d_in[2];
    const float* bf  = (const float*)d_in[3];
    const float* Wxi = (const float*)d_in[4];
    const float* Whi = (const float*)d_in[5];
    const float* bi  = (const float*)d_in[6];
    const float* Wxo = (const float*)d_in[7];
    const float* Who = (const float*)d_in[8];
    const float* bo  = (const float*)d_in[9];
    const float* Wxc = (const float*)d_in[10];
    const float* Whc = (const float*)d_in[11];
    const float* bc  = (const float*)d_in[12];
    float* out = (float*)d_out;

    cudaFuncSetAttribute(xgemm_kernel,
                         cudaFuncAttributeMaxDynamicSharedMemorySize, XG_SMEM);
    cudaFuncSetAttribute(lstm_rec_kernel,
                         cudaFuncAttributeMaxDynamicSharedMemorySize, REC_SMEM);

    dim3 grid1(GDIM / 128, (T_STEPS * BATCH) / 128);
    xgemm_kernel<<<grid1, 256, XG_SMEM>>>(X, Wxf, Wxi, Wxo, Wxc, bf, bi, bo, bc);
    lstm_rec_kernel<<<NCTA_REC, REC_THREADS, REC_SMEM>>>(out, Whf, Whi, Who, Whc);
}

// round 7
// speedup vs baseline: 3.0010x; 1.0362x over previous
#include <cuda_runtime.h>
#include <cstdint>
#include <cstddef>

#define T_STEPS 2048
#define BATCH   64
#define IDIM    512
#define HDIM    512
#define GDIM    2048                 // 4*H, gate order [f|i|o|c]
#define BH      (BATCH * HDIM)       // 32768
#define NCTA_REC 128

// 1 GiB scratch for precomputed input-side gates Xg[t, b, 4H] (fp32, bias folded in)
__device__ float g_Xg[(size_t)T_STEPS * BATCH * GDIM];
// h exchange buffers in exact tf32 B-fragment layout: [parity][group][8192 words]
__device__ unsigned g_hfrag[2][4][8192];
// per-CTA arrival flags, 128B-strided: [group][jt][pad]
__device__ unsigned g_flags[4][32][32];

__device__ __forceinline__ unsigned f2tf32(float x) {
    unsigned r;
    asm("cvt.rna.tf32.f32 %0, %1;" : "=r"(r) : "f"(x));
    return r;
}
__device__ __forceinline__ float tanh_f(float x) {
    float y;
    asm("tanh.approx.f32 %0, %1;" : "=f"(y) : "f"(x));
    return y;
}
__device__ __forceinline__ unsigned ld_acq(const unsigned* p) {
    unsigned v;
    asm volatile("ld.global.acquire.gpu.u32 %0, [%1];" : "=r"(v) : "l"(p) : "memory");
    return v;
}
__device__ __forceinline__ void st_rel(unsigned* p, unsigned v) {
    asm volatile("st.global.release.gpu.u32 [%0], %1;" :: "l"(p), "r"(v) : "memory");
}
__device__ __forceinline__ void cp16(void* dst_smem, const void* src) {
    unsigned d = (unsigned)__cvta_generic_to_shared(dst_smem);
    asm volatile("cp.async.ca.shared.global [%0], [%1], 16;" :: "r"(d), "l"(src));
}
__device__ __forceinline__ void cp_commit() {
    asm volatile("cp.async.commit_group;");
}
__device__ __forceinline__ void cp_wait0() {
    asm volatile("cp.async.wait_group 0;");
}
__device__ __forceinline__ void cp_wait1() {
    asm volatile("cp.async.wait_group 1;");
}

__device__ __forceinline__ void mma_tf32(float &d0, float &d1, float &d2, float &d3,
                                         unsigned a0, unsigned a1, unsigned a2, unsigned a3,
                                         unsigned b0, unsigned b1) {
    asm volatile(
        "mma.sync.aligned.m16n8k8.row.col.f32.tf32.tf32.f32 "
        "{%0,%1,%2,%3}, {%4,%5,%6,%7}, {%8,%9}, {%0,%1,%2,%3};\n"
        : "+f"(d0), "+f"(d1), "+f"(d2), "+f"(d3)
        : "r"(a0), "r"(a1), "r"(a2), "r"(a3), "r"(b0), "r"(b1));
}

// ===========================================================================
// Phase 1: Xg = X @ Wx + b  ([131072 x 512] @ [512 x 2048])  (unchanged R6)
// ===========================================================================
#define XA_STRIDE 36
#define XB_STRIDE 136
#define XA_WORDS (128 * XA_STRIDE)          // 4608
#define XB_WORDS (32 * XB_STRIDE)           // 4352
#define XBUF_WORDS (XA_WORDS + XB_WORDS)    // 8960
#define XG_SMEM (2 * XBUF_WORDS * 4)        // 71680 B

__device__ __forceinline__ void xg_issue(const float* __restrict__ X,
                                         const float* __restrict__ Wx,
                                         int m0, int col0, int k0, int tid,
                                         float* As, float* Bs)
{
    #pragma unroll
    for (int i = 0; i < 4; i++) {
        int idx = tid + i * 256;
        int r = idx >> 3;
        int c4 = (idx & 7) * 4;
        cp16(As + r * XA_STRIDE + c4, X + (size_t)(m0 + r) * IDIM + k0 + c4);
    }
    #pragma unroll
    for (int i = 0; i < 4; i++) {
        int idx = tid + i * 256;
        int kr = idx >> 5;
        int nf = (idx & 31) * 4;
        cp16(Bs + kr * XB_STRIDE + nf, Wx + (size_t)(k0 + kr) * HDIM + col0 + nf);
    }
}

__global__ void __launch_bounds__(256, 2) xgemm_kernel(
    const float* __restrict__ X,
    const float* __restrict__ Wxf, const float* __restrict__ Wxi,
    const float* __restrict__ Wxo, const float* __restrict__ Wxc,
    const float* __restrict__ bf, const float* __restrict__ bi,
    const float* __restrict__ bo, const float* __restrict__ bc)
{
    extern __shared__ float xsm[];

    const int tid  = threadIdx.x;
    const int warp = tid >> 5;
    const int lane = tid & 31;
    const int m0 = blockIdx.y * 128;
    const int n0 = blockIdx.x * 128;
    const int wm = (warp >> 2) * 64;
    const int wn = (warp & 3) * 32;

    if (blockIdx.x == 0 && blockIdx.y == 0) {
        unsigned* f = reinterpret_cast<unsigned*>(g_flags);
        for (int i = tid; i < 4 * 32 * 32; i += 256) f[i] = 0u;
    }

    const int g    = n0 >> 9;
    const int col0 = n0 & 511;
    const float* Wx = (g == 0) ? Wxf : (g == 1) ? Wxi : (g == 2) ? Wxo : Wxc;
    const float* bb = (g == 0) ? bf  : (g == 1) ? bi  : (g == 2) ? bo  : bc;

    float acc[4][4][4];
    #pragma unroll
    for (int mt = 0; mt < 4; mt++)
        #pragma unroll
        for (int nt = 0; nt < 4; nt++)
            #pragma unroll
            for (int e = 0; e < 4; e++) acc[mt][nt][e] = 0.f;

    xg_issue(X, Wx, m0, col0, 0, tid, xsm, xsm + XA_WORDS);
    cp_commit();

    #pragma unroll 1
    for (int kc = 0; kc < 16; kc++) {
        if (kc < 15) {
            float* nb = xsm + ((kc + 1) & 1) * XBUF_WORDS;
            xg_issue(X, Wx, m0, col0, (kc + 1) * 32, tid, nb, nb + XA_WORDS);
            cp_commit();
            cp_wait1();
        } else {
            cp_wait0();
        }
        __syncthreads();

        const unsigned* Au = reinterpret_cast<const unsigned*>(xsm + (kc & 1) * XBUF_WORDS);
        const unsigned* Bu = Au + XA_WORDS;

        #pragma unroll
        for (int kk = 0; kk < 32; kk += 8) {
            unsigned a[4][4], b[4][2];
            const int kcol = kk + (lane & 3);
            #pragma unroll
            for (int mt = 0; mt < 4; mt++) {
                int r = wm + mt * 16 + (lane >> 2);
                a[mt][0] = Au[r * XA_STRIDE + kcol];
                a[mt][1] = Au[(r + 8) * XA_STRIDE + kcol];
                a[mt][2] = Au[r * XA_STRIDE + kcol + 4];
                a[mt][3] = Au[(r + 8) * XA_STRIDE + kcol + 4];
            }
            #pragma unroll
            for (int nt = 0; nt < 4; nt++) {
                int n = wn + nt * 8 + (lane >> 2);
                b[nt][0] = Bu[kcol * XB_STRIDE + n];
                b[nt][1] = Bu[(kcol + 4) * XB_STRIDE + n];
            }
            #pragma unroll
            for (int mt = 0; mt < 4; mt++)
                #pragma unroll
                for (int nt = 0; nt < 4; nt++)
                    mma_tf32(acc[mt][nt][0], acc[mt][nt][1], acc[mt][nt][2], acc[mt][nt][3],
                             a[mt][0], a[mt][1], a[mt][2], a[mt][3],
                             b[nt][0], b[nt][1]);
        }
        __syncthreads();
    }

    #pragma unroll
    for (int mt = 0; mt < 4; mt++) {
        #pragma unroll
        for (int nt = 0; nt < 4; nt++) {
            int nloc = wn + nt * 8 + (lane & 3) * 2;
            int r = m0 + wm + mt * 16 + (lane >> 2);
            float bv0 = bb[col0 + nloc];
            float bv1 = bb[col0 + nloc + 1];
            float2 v0 = make_float2(acc[mt][nt][0] + bv0, acc[mt][nt][1] + bv1);
            float2 v1 = make_float2(acc[mt][nt][2] + bv0, acc[mt][nt][3] + bv1);
            *reinterpret_cast<float2*>(&g_Xg[(size_t)r * GDIM + n0 + nloc]) = v0;
            *reinterpret_cast<float2*>(&g_Xg[(size_t)(r + 8) * GDIM + n0 + nloc]) = v1;
        }
    }
}

// ===========================================================================
// Phase 2: persistent recurrence. 128 CTAs = 4 groups x 32 hidden tiles,
// 256 threads = 8 warps = 2 M-tiles(32 gate-cols) x 4 K-splits(128).
// W_h entirely in registers (128 regs/thread, static-indexed).
// h B-fragments loaded DIRECTLY from g_hfrag via LDG (no smem staging):
// per warp 16 ki x LDG.128, 4 interleaved mma chains (2 tiles x 2 batch-halves).
// Per-step smem traffic ~20KB (was ~200KB in R6).
// ===========================================================================
#define REC_THREADS 256
#define GS2_WORDS (4 * 64 * 18)                       // [ks][gatecol][batch pad18]
#define REC_SMEM (GS2_WORDS * 4 + 1024)               // gs2 + pub

__global__ void __launch_bounds__(256, 1) lstm_rec_kernel(
    float* __restrict__ out,
    const float* __restrict__ Whf, const float* __restrict__ Whi,
    const float* __restrict__ Who, const float* __restrict__ Whc)
{
    extern __shared__ unsigned char smem_raw[];
    float* gs2 = reinterpret_cast<float*>(smem_raw);                       // [4][64][18]
    unsigned* pub = reinterpret_cast<unsigned*>(smem_raw + GS2_WORDS * 4); // 256 words

    const int tid  = threadIdx.x;
    const int warp = tid >> 5;
    const int lane = tid & 31;
    const int bt = blockIdx.x >> 5;   // batch group 0..3 (16 rows)
    const int jt = blockIdx.x & 31;   // hidden tile 0..31 (16 cols)

    const int mt = warp >> 2;         // M half: gates {f,i} (0) or {o,c} (1)
    const int ks = warp & 3;          // K chunk 0..3 (128 each)

    // ---- one-time: W_h A-fragments into registers (2 tiles x 16 ki x 4) ----
    unsigned Wr0[16][4], Wr1[16][4];
    {
        const float* Wh0 = (mt == 0) ? Whf : Who;   // tile 0 -> gate mt*2
        const float* Wh1 = (mt == 0) ? Whi : Whc;   // tile 1 -> gate mt*2+1
        const int colA = jt * 16 + (lane >> 2);
        #pragma unroll
        for (int ki = 0; ki < 16; ki++) {
            int k = ks * 128 + ki * 8 + (lane & 3);
            Wr0[ki][0] = f2tf32(Wh0[(size_t)k * HDIM + colA]);
            Wr0[ki][1] = f2tf32(Wh0[(size_t)k * HDIM + colA + 8]);
            Wr0[ki][2] = f2tf32(Wh0[(size_t)(k + 4) * HDIM + colA]);
            Wr0[ki][3] = f2tf32(Wh0[(size_t)(k + 4) * HDIM + colA + 8]);
            Wr1[ki][0] = f2tf32(Wh1[(size_t)k * HDIM + colA]);
            Wr1[ki][1] = f2tf32(Wh1[(size_t)k * HDIM + colA + 8]);
            Wr1[ki][2] = f2tf32(Wh1[(size_t)(k + 4) * HDIM + colA]);
            Wr1[ki][3] = f2tf32(Wh1[(size_t)(k + 4) * HDIM + colA + 8]);
        }
    }

    // cell thread mapping: owns c[bt*16+eb][jt*16+ej]
    const int eb = tid >> 4;
    const int ej = tid & 15;
    float c_val = 0.f;

    // position of h[eb][ej] within CTA's contiguous 1KB B-frag block
    const int lidx = ((ej >> 3) << 7) + (((eb & 7) << 2) + (ej & 3)) * 4
                     + ((eb >> 3) << 1) + ((ej >> 2) & 1);

    // Xg prefetch for t=0
    float xgv[4];
    {
        size_t xb = ((size_t)bt * 16 + eb) * GDIM + jt * 16 + ej;
        #pragma unroll
        for (int g = 0; g < 4; g++) xgv[g] = g_Xg[xb + g * HDIM];
    }
    __syncthreads();

    #pragma unroll 1
    for (int t = 0; t < T_STEPS; t++) {
        // ---- recurrent mma: B frags direct from global, W from registers ----
        float A00[4] = {0.f,0.f,0.f,0.f}, A01[4] = {0.f,0.f,0.f,0.f};
        float A10[4] = {0.f,0.f,0.f,0.f}, A11[4] = {0.f,0.f,0.f,0.f};
        if (t > 0) {
            const uint4* hp = reinterpret_cast<const uint4*>(g_hfrag[(t - 1) & 1][bt])
                              + ks * 512 + lane;
            #pragma unroll
            for (int half = 0; half < 2; half++) {
                uint4 hbuf[8];
                #pragma unroll
                for (int i = 0; i < 8; i++)
                    hbuf[i] = __ldcg(hp + (half * 8 + i) * 32);
                #pragma unroll
                for (int ki = 0; ki < 8; ki++) {
                    int kg = half * 8 + ki;
                    uint4 hb = hbuf[ki];
                    mma_tf32(A00[0], A00[1], A00[2], A00[3],
                             Wr0[kg][0], Wr0[kg][1], Wr0[kg][2], Wr0[kg][3], hb.x, hb.y);
                    mma_tf32(A01[0], A01[1], A01[2], A01[3],
                             Wr0[kg][0], Wr0[kg][1], Wr0[kg][2], Wr0[kg][3], hb.z, hb.w);
                    mma_tf32(A10[0], A10[1], A10[2], A10[3],
                             Wr1[kg][0], Wr1[kg][1], Wr1[kg][2], Wr1[kg][3], hb.x, hb.y);
                    mma_tf32(A11[0], A11[1], A11[2], A11[3],
                             Wr1[kg][0], Wr1[kg][1], Wr1[kg][2], Wr1[kg][3], hb.z, hb.w);
                }
            }
        }

        // ---- K-partials to smem: [ks][gatecol][batch] ----
        {
            const int r  = lane >> 2;
            const int c2 = (lane & 3) * 2;
            float* g0 = gs2 + (ks * 64 + mt * 32) * 18;        // tile 0 cols
            float* g1 = g0 + 16 * 18;                          // tile 1 cols
            *reinterpret_cast<float2*>(&g0[r * 18 + c2])           = make_float2(A00[0], A00[1]);
            *reinterpret_cast<float2*>(&g0[(r + 8) * 18 + c2])     = make_float2(A00[2], A00[3]);
            *reinterpret_cast<float2*>(&g0[r * 18 + 8 + c2])       = make_float2(A01[0], A01[1]);
            *reinterpret_cast<float2*>(&g0[(r + 8) * 18 + 8 + c2]) = make_float2(A01[2], A01[3]);
            *reinterpret_cast<float2*>(&g1[r * 18 + c2])           = make_float2(A10[0], A10[1]);
            *reinterpret_cast<float2*>(&g1[(r + 8) * 18 + c2])     = make_float2(A10[2], A10[3]);
            *reinterpret_cast<float2*>(&g1[r * 18 + 8 + c2])       = make_float2(A11[0], A11[1]);
            *reinterpret_cast<float2*>(&g1[(r + 8) * 18 + 8 + c2]) = make_float2(A11[2], A11[3]);
        }
        __syncthreads();

        // ---- cell: reduce 4 K-partials per gate + LSTM nonlinearity ----
        float hv;
        {
            float gate[4];
            #pragma unroll
            for (int g = 0; g < 4; g++) {
                float s = xgv[g];
                #pragma unroll
                for (int k = 0; k < 4; k++)
                    s += gs2[(k * 64 + g * 16 + ej) * 18 + eb];
                gate[g] = s;
            }
            float fg = 0.5f * tanh_f(0.5f * gate[0]) + 0.5f;
            float ig = 0.5f * tanh_f(0.5f * gate[1]) + 0.5f;
            float og = 0.5f * tanh_f(0.5f * gate[2]) + 0.5f;
            float ch = tanh_f(gate[3]);
            c_val = fg * c_val + ig * ch;
            hv = og * tanh_f(c_val);
            pub[lidx] = f2tf32(hv);
        }
        __syncthreads();

        // ---- warp0 publishes contiguous 1KB + releases flag ----
        if (warp == 0) {
            uint4* dst = reinterpret_cast<uint4*>(&g_hfrag[t & 1][bt][jt * 256]);
            const uint4* ps = reinterpret_cast<const uint4*>(pub);
            dst[lane]      = ps[lane];
            dst[lane + 32] = ps[lane + 32];
            __syncwarp();
            if (lane == 0 && t + 1 < T_STEPS) {
                __threadfence();
                st_rel(&g_flags[bt][jt][0], (unsigned)(t + 1));
            }
        }

        // ---- off-critical-path output + next-step Xg prefetch ----
        {
            size_t oidx = (size_t)t * BH + (size_t)(bt * 16 + eb) * HDIM + (size_t)jt * 16 + ej;
            out[oidx] = hv;
            if (t == T_STEPS - 1) {
                size_t tail = (size_t)T_STEPS * BH + (size_t)(bt * 16 + eb) * HDIM + (size_t)jt * 16 + ej;
                out[tail]      = hv;      // h_T
                out[tail + BH] = c_val;   // c_T
            }
            if (t + 1 < T_STEPS) {
                size_t xb = ((size_t)(t + 1) * BATCH + (size_t)bt * 16 + eb) * GDIM + jt * 16 + ej;
                #pragma unroll
                for (int g = 0; g < 4; g++) xgv[g] = g_Xg[xb + g * HDIM];
            }
        }

        // ---- group barrier (32 CTAs of this batch group) ----
        if (t + 1 < T_STEPS) {
            if (tid < 32) {
                const unsigned* fp = &g_flags[bt][tid][0];
                while (ld_acq(fp) < (unsigned)(t + 1)) { }
            }
            __syncthreads();
        }
    }
}

// ===========================================================================
extern "C" void kernel_launch(void* const* d_in, const int* in_sizes, int n_in,
                              void* d_out, int out_size)
{
    const float* X   = (const float*)d_in[0];
    const float* Wxf = (const float*)d_in[1];
    const float* Whf = (const float*)d_in[2];
    const float* bf  = (const float*)d_in[3];
    const float* Wxi = (const float*)d_in[4];
    const float* Whi = (const float*)d_in[5];
    const float* bi  = (const float*)d_in[6];
    const float* Wxo = (const float*)d_in[7];
    const float* Who = (const float*)d_in[8];
    const float* bo  = (const float*)d_in[9];
    const float* Wxc = (const float*)d_in[10];
    const float* Whc = (const float*)d_in[11];
    const float* bc  = (const float*)d_in[12];
    float* out = (float*)d_out;

    cudaFuncSetAttribute(xgemm_kernel,
                         cudaFuncAttributeMaxDynamicSharedMemorySize, XG_SMEM);
    cudaFuncSetAttribute(lstm_rec_kernel,
                         cudaFuncAttributeMaxDynamicSharedMemorySize, REC_SMEM);

    dim3 grid1(GDIM / 128, (T_STEPS * BATCH) / 128);
    xgemm_kernel<<<grid1, 256, XG_SMEM>>>(X, Wxf, Wxi, Wxo, Wxc, bf, bi, bo, bc);
    lstm_rec_kernel<<<NCTA_REC, REC_THREADS, REC_SMEM>>>(out, Whf, Whi, Who, Whc);
}